// round 15
// baseline (speedup 1.0000x reference)
#include <cuda_runtime.h>
#include <cuda_bf16.h>
#include <cuda_fp16.h>
#include <cstdint>

// BatchSRU: L=2048, B=8, D=128, NB=16, fp32.
// x_tilde: 3-combo bf16 hi/lo HMMA; f,r: single fp16 HMMA.
// R14 skeleton with NT=32: 384 threads; warps 4-11 GEMM (1 x~ mtile 3-combo +
// 1 f + 1 r mtile fp16, 4 n8-tiles), warps 0-3 scan tile i-1 concurrently.
// Pass1: transpose+split -> g_xhi/g_xlo (bf16) + g_xh (fp16).
// Pass3: untranspose g_hT -> out.

#define L_SEQ 2048
#define BATCH 8
#define DIM   128
#define NBI   16
#define NT    32
#define NTILES 64

__device__ __nv_bfloat16 g_xhi[BATCH * NBI * L_SEQ * DIM];
__device__ __nv_bfloat16 g_xlo[BATCH * NBI * L_SEQ * DIM];
__device__ __half        g_xh [BATCH * NBI * L_SEQ * DIM];
__device__ float         g_hT [BATCH * NBI * L_SEQ * DIM];

// SMEM: W resident 128K + XB 2x24K + U 32K = 208K
#define OFF_WXHI 0            // 128 rows x 256 B
#define OFF_WXLO 32768
#define OFF_WF   65536        // fp16 f-gate W
#define OFF_WR2  98304        // fp16 r-gate W
#define OFF_XB   131072       // 2 bufs x 24576: [xhi 8192][xlo 8192][xh 8192]
#define OFF_UX   180224       // fp32 [32][128]
#define OFF_UF   196608       // fp16 [32][128]
#define OFF_UR   204800       // fp16 [32][128]
#define SMEM_MAIN 212992

__device__ __forceinline__ uint32_t smem_u32(const void* p) {
    uint32_t a;
    asm("{ .reg .u64 t; cvta.to.shared.u64 t, %1; cvt.u32.u64 %0, t; }" : "=r"(a) : "l"(p));
    return a;
}
__device__ __forceinline__ void ldsm_x4(uint32_t* r, uint32_t addr) {
    asm volatile("ldmatrix.sync.aligned.m8n8.x4.shared.b16 {%0,%1,%2,%3}, [%4];"
                 : "=r"(r[0]), "=r"(r[1]), "=r"(r[2]), "=r"(r[3]) : "r"(addr));
}
__device__ __forceinline__ void ldsm_x2(uint32_t* r, uint32_t addr) {
    asm volatile("ldmatrix.sync.aligned.m8n8.x2.shared.b16 {%0,%1}, [%2];"
                 : "=r"(r[0]), "=r"(r[1]) : "r"(addr));
}
__device__ __forceinline__ void mma_bf16(float* d, const uint32_t* a, const uint32_t* b) {
    asm volatile("mma.sync.aligned.m16n8k16.row.col.f32.bf16.bf16.f32 "
                 "{%0,%1,%2,%3}, {%4,%5,%6,%7}, {%8,%9}, {%0,%1,%2,%3};"
                 : "+f"(d[0]), "+f"(d[1]), "+f"(d[2]), "+f"(d[3])
                 : "r"(a[0]), "r"(a[1]), "r"(a[2]), "r"(a[3]), "r"(b[0]), "r"(b[1]));
}
__device__ __forceinline__ void mma_f16(float* d, const uint32_t* a, const uint32_t* b) {
    asm volatile("mma.sync.aligned.m16n8k16.row.col.f32.f16.f16.f32 "
                 "{%0,%1,%2,%3}, {%4,%5,%6,%7}, {%8,%9}, {%0,%1,%2,%3};"
                 : "+f"(d[0]), "+f"(d[1]), "+f"(d[2]), "+f"(d[3])
                 : "r"(a[0]), "r"(a[1]), "r"(a[2]), "r"(a[3]), "r"(b[0]), "r"(b[1]));
}
__device__ __forceinline__ float sigf(float z) {
    return __fdividef(1.0f, 1.0f + __expf(-z));
}

// ============ Pass 1: transpose + bf16 split + fp16 copy ============
#define TP_T 4
__global__ void __launch_bounds__(256) transpose_x(const float* __restrict__ x) {
    __shared__ float sm[TP_T * 16 * 129];
    const int bx = blockIdx.x;
    const int t0 = (bx >> 3) * TP_T;
    const int b  = bx & 7;
    #pragma unroll 4
    for (int i = 0; i < 32; i++) {
        int idx  = i * 256 + threadIdx.x;
        int tloc = idx >> 11;
        int rem  = idx & 2047;                  // k*16 + nb
        float v = x[((size_t)(t0 + tloc) * BATCH + b) * 2048 + rem];
        sm[(tloc * 16 + (rem & 15)) * 129 + (rem >> 4)] = v;
    }
    __syncthreads();
    #pragma unroll 4
    for (int i = 0; i < 32; i++) {
        int idx = i * 256 + threadIdx.x;
        int k = idx & 127;
        int chunk = idx >> 7;                   // nb*4 + tloc
        int nb = chunk >> 2, tloc = chunk & 3;
        float v = sm[(tloc * 16 + nb) * 129 + k];
        __nv_bfloat16 hi = __float2bfloat16(v);
        __nv_bfloat16 lo = __float2bfloat16(v - __bfloat162float(hi));
        size_t o = ((size_t)(b * NBI + nb) * L_SEQ + t0 + tloc) * DIM + k;
        g_xhi[o] = hi;
        g_xlo[o] = lo;
        g_xh[o]  = __float2half(v);
    }
}

// ============ Pass 3: untranspose h ============
__global__ void __launch_bounds__(256) untranspose_h(float* __restrict__ out) {
    __shared__ float sm[TP_T * 16 * 129];
    const int bx = blockIdx.x;
    const int t0 = (bx >> 3) * TP_T;
    const int b  = bx & 7;
    #pragma unroll 4
    for (int i = 0; i < 32; i++) {
        int idx = i * 256 + threadIdx.x;
        int k = idx & 127;
        int chunk = idx >> 7;
        int nb = chunk >> 2, tloc = chunk & 3;
        sm[(tloc * 16 + nb) * 129 + k] =
            g_hT[((size_t)(b * NBI + nb) * L_SEQ + t0 + tloc) * DIM + k];
    }
    __syncthreads();
    #pragma unroll 4
    for (int i = 0; i < 32; i++) {
        int idx  = i * 256 + threadIdx.x;
        int tloc = idx >> 11;
        int rem  = idx & 2047;
        out[((size_t)(t0 + tloc) * BATCH + b) * 2048 + rem] =
            sm[(tloc * 16 + (rem & 15)) * 129 + (rem >> 4)];
    }
}

// ============ Pass 2: main (384 threads) ============
__global__ void __launch_bounds__(384, 1) sru_main(
    const float* __restrict__ W, const float* __restrict__ bias)
{
    extern __shared__ char sm[];
    const uint32_t sb = smem_u32(sm);
    const int tid  = threadIdx.x;
    const int lane = tid & 31;
    const int wid  = tid >> 5;
    const int bx = blockIdx.x, nb = bx & 15;
    const bool is_scan = (tid < 128);

    // lane constants
    const int a_tile    = lane >> 3;
    const int a_row_add = (lane & 7) + ((a_tile & 1) << 3);
    const int a_chalf   = a_tile >> 1;
    const int b_row     = lane & 7;
    const int b_chalf   = (lane >> 3) & 1;
    const int g  = lane >> 2;
    const int tg = lane & 3;
    const int wg = wid - 4;                      // GEMM warp 0..7

    // ---- startup: stage W (thread owns column h = tid, 0..383)
    {
        const float* Wp = W + (size_t)nb * (DIM * 3 * DIM);
        const int h = tid;
        const int lr = h & 127;
        const uint32_t rowswz = (uint32_t)(lr & 15);
        if (h < 128) {
            #pragma unroll 4
            for (int k = 0; k < 128; k++) {
                float v = Wp[k * 384 + h];
                __nv_bfloat16 hi = __float2bfloat16(v);
                __nv_bfloat16 lo = __float2bfloat16(v - __bfloat162float(hi));
                uint32_t sw = (uint32_t)((((k >> 3) ^ rowswz) << 4) + ((k & 7) * 2));
                *(__nv_bfloat16*)(sm + OFF_WXHI + lr * 256 + sw) = hi;
                *(__nv_bfloat16*)(sm + OFF_WXLO + lr * 256 + sw) = lo;
            }
        } else {
            const uint32_t base = (h < 256) ? OFF_WF : OFF_WR2;
            #pragma unroll 4
            for (int k = 0; k < 128; k++) {
                float v = Wp[k * 384 + h];
                uint32_t sw = (uint32_t)((((k >> 3) ^ rowswz) << 4) + ((k & 7) * 2));
                *(__half*)(sm + base + lr * 256 + sw) = __float2half(v);
            }
        }
    }
    // ---- scan init + stage XB(0)
    const int j = tid;                           // channel (scan threads)
    float bfv = 0.0f, brv = 0.0f;
    if (is_scan) {
        bfv = bias[nb * 256 + j];
        brv = bias[nb * 256 + 128 + j];
        // thread covers row t = tid>>2, chunks 4q..4q+3 (q = tid&3)
        int t = tid >> 2, q = tid & 3;
        size_t o = ((size_t)bx * L_SEQ + t) * DIM + q * 32;
        uint32_t base = OFF_XB + (uint32_t)t * 256;
        #pragma unroll
        for (int p = 0; p < 4; p++) {
            int cc = q * 4 + p;
            uint32_t sw = (uint32_t)((cc ^ (t & 15)) << 4);
            *(uint4*)(sm + base + sw)        = *(const uint4*)(g_xhi + o + p * 8);
            *(uint4*)(sm + base + 8192 + sw) = *(const uint4*)(g_xlo + o + p * 8);
            *(uint4*)(sm + base + 16384 + sw) = *(const uint4*)(g_xh + o + p * 8);
        }
    }
    float c = 0.0f;
    float xt[NT], xv[NT];
    __half fh[NT], rh[NT];
    __syncthreads();

    for (int i = 0; i < NTILES; i++) {
        const int buf = i & 1;
        uint4 pfh[4], pfl[4], pff[4];            // scan-thread prefetch regs

        if (!is_scan) {
            // ---------- GEMM(i): warp wg owns x~-mtile wg, f-mtile wg, r-mtile wg
            float Dx[4][4], Df[4][4], Dr[4][4];
            #pragma unroll
            for (int nt = 0; nt < 4; nt++)
                #pragma unroll
                for (int e = 0; e < 4; e++) { Dx[nt][e] = 0.0f; Df[nt][e] = 0.0f; Dr[nt][e] = 0.0f; }

            const uint32_t xb = sb + OFF_XB + (uint32_t)buf * 24576;
            const int arow = wg * 16 + a_row_add;
            #pragma unroll
            for (int ks = 0; ks < 8; ks++) {
                uint32_t Bhi[4][2], Blo[4][2], Bf[4][2];
                #pragma unroll
                for (int nt = 0; nt < 4; nt++) {
                    int trow = nt * 8 + b_row;
                    uint32_t ba = xb + trow * 256 + (((2 * ks + b_chalf) ^ (trow & 15)) << 4);
                    ldsm_x2(Bhi[nt], ba);
                    ldsm_x2(Blo[nt], ba + 8192);
                    ldsm_x2(Bf[nt],  ba + 16384);
                }
                uint32_t aoff = (uint32_t)(arow * 256 + (((2 * ks + a_chalf) ^ (arow & 15)) << 4));
                uint32_t Axh[4], Axl[4], Af[4], Ar[4];
                ldsm_x4(Axh, sb + OFF_WXHI + aoff);
                ldsm_x4(Axl, sb + OFF_WXLO + aoff);
                ldsm_x4(Af,  sb + OFF_WF   + aoff);
                ldsm_x4(Ar,  sb + OFF_WR2  + aoff);
                #pragma unroll
                for (int nt = 0; nt < 4; nt++) {
                    mma_bf16(Dx[nt], Axh, Bhi[nt]);
                    mma_bf16(Dx[nt], Axl, Bhi[nt]);
                    mma_bf16(Dx[nt], Axh, Blo[nt]);
                    mma_f16(Df[nt], Af, Bf[nt]);
                    mma_f16(Dr[nt], Ar, Bf[nt]);
                }
            }
            // -- store U(i)
            {
                int h0 = wg * 16 + g;
                float*  ux = (float*)(sm + OFF_UX);
                __half* uf = (__half*)(sm + OFF_UF);
                __half* ur = (__half*)(sm + OFF_UR);
                #pragma unroll
                for (int nt = 0; nt < 4; nt++) {
                    int t0 = nt * 8 + tg * 2;
                    ux[(t0)     * DIM + h0]     = Dx[nt][0];
                    ux[(t0 + 1) * DIM + h0]     = Dx[nt][1];
                    ux[(t0)     * DIM + h0 + 8] = Dx[nt][2];
                    ux[(t0 + 1) * DIM + h0 + 8] = Dx[nt][3];
                    uf[(t0)     * DIM + h0]     = __float2half_rn(Df[nt][0]);
                    uf[(t0 + 1) * DIM + h0]     = __float2half_rn(Df[nt][1]);
                    uf[(t0)     * DIM + h0 + 8] = __float2half_rn(Df[nt][2]);
                    uf[(t0 + 1) * DIM + h0 + 8] = __float2half_rn(Df[nt][3]);
                    ur[(t0)     * DIM + h0]     = __float2half_rn(Dr[nt][0]);
                    ur[(t0 + 1) * DIM + h0]     = __float2half_rn(Dr[nt][1]);
                    ur[(t0)     * DIM + h0 + 8] = __float2half_rn(Dr[nt][2]);
                    ur[(t0 + 1) * DIM + h0 + 8] = __float2half_rn(Dr[nt][3]);
                }
            }
        } else {
            // ---------- scan(i-1) + LDG prefetch x(i+1), concurrent with GEMM(i)
            if (i + 1 < NTILES) {
                int t = tid >> 2, q = tid & 3;
                size_t o = ((size_t)bx * L_SEQ + (size_t)(i + 1) * NT + t) * DIM + q * 32;
                #pragma unroll
                for (int p = 0; p < 4; p++) {
                    pfh[p] = *(const uint4*)(g_xhi + o + p * 8);
                    pfl[p] = *(const uint4*)(g_xlo + o + p * 8);
                    pff[p] = *(const uint4*)(g_xh + o + p * 8);
                }
            }
            if (i > 0) {
                float* hp = g_hT + ((size_t)bx * L_SEQ + (size_t)(i - 1) * NT) * DIM + j;
                #pragma unroll
                for (int t = 0; t < NT; t++) {
                    float fv = sigf(__half2float(fh[t]) + bfv);
                    float rv = sigf(__half2float(rh[t]) + brv);
                    c = fmaf(fv, c - xt[t], xt[t]);
                    hp[t * DIM] = fmaf(rv, c - xv[t], xv[t]);
                }
            }
        }
        __syncthreads();                         // U(i) visible; scan(i-1) done

        if (is_scan) {
            // -- stage XB(i+1)
            if (i + 1 < NTILES) {
                int t = tid >> 2, q = tid & 3;
                uint32_t base = OFF_XB + (uint32_t)((i + 1) & 1) * 24576 + (uint32_t)t * 256;
                #pragma unroll
                for (int p = 0; p < 4; p++) {
                    int cc = q * 4 + p;
                    uint32_t sw = (uint32_t)((cc ^ (t & 15)) << 4);
                    *(uint4*)(sm + base + sw)         = pfh[p];
                    *(uint4*)(sm + base + 8192 + sw)  = pfl[p];
                    *(uint4*)(sm + base + 16384 + sw) = pff[p];
                }
            }
            // -- drain U(i) and xv(i) into registers
            const float*  ux = (const float*)(sm + OFF_UX);
            const __half* uf = (const __half*)(sm + OFF_UF);
            const __half* ur = (const __half*)(sm + OFF_UR);
            const uint32_t xbb = OFF_XB + (uint32_t)buf * 24576;
            #pragma unroll
            for (int t = 0; t < NT; t++) {
                xt[t] = ux[t * DIM + j];
                fh[t] = uf[t * DIM + j];
                rh[t] = ur[t * DIM + j];
                uint32_t xa = xbb + t * 256 + (((j >> 3) ^ (t & 15)) << 4) + ((j & 7) * 2);
                xv[t] = __bfloat162float(*(__nv_bfloat16*)(sm + xa)) +
                        __bfloat162float(*(__nv_bfloat16*)(sm + xa + 8192));
            }
        }
        __syncthreads();                         // U free; XB((i+1)&1) staged
    }

    // -- final scan(NTILES-1)
    if (is_scan) {
        float* hp = g_hT + ((size_t)bx * L_SEQ + (size_t)(NTILES - 1) * NT) * DIM + j;
        #pragma unroll
        for (int t = 0; t < NT; t++) {
            float fv = sigf(__half2float(fh[t]) + bfv);
            float rv = sigf(__half2float(rh[t]) + brv);
            c = fmaf(fv, c - xt[t], xt[t]);
            hp[t * DIM] = fmaf(rv, c - xv[t], xv[t]);
        }
    }
}

extern "C" void kernel_launch(void* const* d_in, const int* in_sizes, int n_in,
                              void* d_out, int out_size) {
    const float* x  = (const float*)d_in[0];
    const float* W  = (const float*)d_in[1];
    const float* bi = (const float*)d_in[2];
    float* out = (float*)d_out;

    transpose_x<<<(L_SEQ / TP_T) * BATCH, 256>>>(x);
    cudaFuncSetAttribute(sru_main, cudaFuncAttributeMaxDynamicSharedMemorySize, SMEM_MAIN);
    sru_main<<<BATCH * NBI, 384, SMEM_MAIN>>>(W, bi);
    untranspose_h<<<(L_SEQ / TP_T) * BATCH, 256>>>(out);
}

// round 16
// speedup vs baseline: 1.6748x; 1.6748x over previous
#include <cuda_runtime.h>
#include <cuda_bf16.h>
#include <cuda_fp16.h>
#include <cstdint>

// BatchSRU: L=2048, B=8, D=128, NB=16, fp32.
// x_tilde: 3-combo bf16 hi/lo HMMA; f,r: single fp16 HMMA.
// R14 skeleton (NT=16, 384 threads): warps 4-11 GEMM (1 x~ mtile 3-combo +
// 1 f + 1 r mtile fp16) AND XB staging; warps 0-3 scan tile i-1 concurrently.
// fp16 B operand derived in-register from bf16 hi+lo (no g_xh array).
// Pass1: transpose+split -> g_xhi/g_xlo only. Pass3: untranspose g_hT -> out.

#define L_SEQ 2048
#define BATCH 8
#define DIM   128
#define NBI   16
#define NT    16
#define NTILES 128

__device__ __nv_bfloat16 g_xhi[BATCH * NBI * L_SEQ * DIM];
__device__ __nv_bfloat16 g_xlo[BATCH * NBI * L_SEQ * DIM];
__device__ float         g_hT [BATCH * NBI * L_SEQ * DIM];

// SMEM: W resident 128K + XB 2x12K + U 16K = 172K
#define OFF_WXHI 0            // 128 rows x 256 B
#define OFF_WXLO 32768
#define OFF_WF   65536        // fp16 f-gate W
#define OFF_WR2  98304        // fp16 r-gate W
#define OFF_XB   131072       // 2 bufs x 12288: [xhi 4096][xlo 4096][xh 4096]
#define OFF_UX   155648       // fp32 [16][128]
#define OFF_UF   163840       // fp16 [16][128]
#define OFF_UR   167936       // fp16 [16][128]
#define SMEM_MAIN 172032

__device__ __forceinline__ uint32_t smem_u32(const void* p) {
    uint32_t a;
    asm("{ .reg .u64 t; cvta.to.shared.u64 t, %1; cvt.u32.u64 %0, t; }" : "=r"(a) : "l"(p));
    return a;
}
__device__ __forceinline__ void ldsm_x4(uint32_t* r, uint32_t addr) {
    asm volatile("ldmatrix.sync.aligned.m8n8.x4.shared.b16 {%0,%1,%2,%3}, [%4];"
                 : "=r"(r[0]), "=r"(r[1]), "=r"(r[2]), "=r"(r[3]) : "r"(addr));
}
__device__ __forceinline__ void ldsm_x2(uint32_t* r, uint32_t addr) {
    asm volatile("ldmatrix.sync.aligned.m8n8.x2.shared.b16 {%0,%1}, [%2];"
                 : "=r"(r[0]), "=r"(r[1]) : "r"(addr));
}
__device__ __forceinline__ void mma_bf16(float* d, const uint32_t* a, const uint32_t* b) {
    asm volatile("mma.sync.aligned.m16n8k16.row.col.f32.bf16.bf16.f32 "
                 "{%0,%1,%2,%3}, {%4,%5,%6,%7}, {%8,%9}, {%0,%1,%2,%3};"
                 : "+f"(d[0]), "+f"(d[1]), "+f"(d[2]), "+f"(d[3])
                 : "r"(a[0]), "r"(a[1]), "r"(a[2]), "r"(a[3]), "r"(b[0]), "r"(b[1]));
}
__device__ __forceinline__ void mma_f16(float* d, const uint32_t* a, const uint32_t* b) {
    asm volatile("mma.sync.aligned.m16n8k16.row.col.f32.f16.f16.f32 "
                 "{%0,%1,%2,%3}, {%4,%5,%6,%7}, {%8,%9}, {%0,%1,%2,%3};"
                 : "+f"(d[0]), "+f"(d[1]), "+f"(d[2]), "+f"(d[3])
                 : "r"(a[0]), "r"(a[1]), "r"(a[2]), "r"(a[3]), "r"(b[0]), "r"(b[1]));
}
__device__ __forceinline__ float sigf(float z) {
    return __fdividef(1.0f, 1.0f + __expf(-z));
}
// derive fp16x2 x from packed bf16 hi/lo pairs (hi+lo ~= original fp32)
__device__ __forceinline__ uint4 derive_f16(uint4 H, uint4 L) {
    uint4 F;
    const uint32_t* h = (const uint32_t*)&H;
    const uint32_t* l = (const uint32_t*)&L;
    uint32_t* f = (uint32_t*)&F;
    #pragma unroll
    for (int p = 0; p < 4; p++) {
        float2 hv = __bfloat1622float2(*(const __nv_bfloat162*)&h[p]);
        float2 lv = __bfloat1622float2(*(const __nv_bfloat162*)&l[p]);
        __half2 r = __float22half2_rn(make_float2(hv.x + lv.x, hv.y + lv.y));
        f[p] = *(uint32_t*)&r;
    }
    return F;
}

// ============ Pass 1: transpose + bf16 split ============
#define TP_T 4
__global__ void __launch_bounds__(256) transpose_x(const float* __restrict__ x) {
    __shared__ float sm[TP_T * 16 * 129];
    const int bx = blockIdx.x;
    const int t0 = (bx >> 3) * TP_T;
    const int b  = bx & 7;
    #pragma unroll 4
    for (int i = 0; i < 32; i++) {
        int idx  = i * 256 + threadIdx.x;
        int tloc = idx >> 11;
        int rem  = idx & 2047;                  // k*16 + nb
        float v = x[((size_t)(t0 + tloc) * BATCH + b) * 2048 + rem];
        sm[(tloc * 16 + (rem & 15)) * 129 + (rem >> 4)] = v;
    }
    __syncthreads();
    #pragma unroll 4
    for (int i = 0; i < 32; i++) {
        int idx = i * 256 + threadIdx.x;
        int k = idx & 127;
        int chunk = idx >> 7;                   // nb*4 + tloc
        int nb = chunk >> 2, tloc = chunk & 3;
        float v = sm[(tloc * 16 + nb) * 129 + k];
        __nv_bfloat16 hi = __float2bfloat16(v);
        __nv_bfloat16 lo = __float2bfloat16(v - __bfloat162float(hi));
        size_t o = ((size_t)(b * NBI + nb) * L_SEQ + t0 + tloc) * DIM + k;
        g_xhi[o] = hi;
        g_xlo[o] = lo;
    }
}

// ============ Pass 3: untranspose h ============
__global__ void __launch_bounds__(256) untranspose_h(float* __restrict__ out) {
    __shared__ float sm[TP_T * 16 * 129];
    const int bx = blockIdx.x;
    const int t0 = (bx >> 3) * TP_T;
    const int b  = bx & 7;
    #pragma unroll 4
    for (int i = 0; i < 32; i++) {
        int idx = i * 256 + threadIdx.x;
        int k = idx & 127;
        int chunk = idx >> 7;
        int nb = chunk >> 2, tloc = chunk & 3;
        sm[(tloc * 16 + nb) * 129 + k] =
            g_hT[((size_t)(b * NBI + nb) * L_SEQ + t0 + tloc) * DIM + k];
    }
    __syncthreads();
    #pragma unroll 4
    for (int i = 0; i < 32; i++) {
        int idx  = i * 256 + threadIdx.x;
        int tloc = idx >> 11;
        int rem  = idx & 2047;
        out[((size_t)(t0 + tloc) * BATCH + b) * 2048 + rem] =
            sm[(tloc * 16 + (rem & 15)) * 129 + (rem >> 4)];
    }
}

// ============ Pass 2: main (384 threads) ============
__global__ void __launch_bounds__(384, 1) sru_main(
    const float* __restrict__ W, const float* __restrict__ bias)
{
    extern __shared__ char sm[];
    const uint32_t sb = smem_u32(sm);
    const int tid  = threadIdx.x;
    const int lane = tid & 31;
    const int wid  = tid >> 5;
    const int bx = blockIdx.x, nb = bx & 15;
    const bool is_scan = (tid < 128);

    // lane constants
    const int a_tile    = lane >> 3;
    const int a_row_add = (lane & 7) + ((a_tile & 1) << 3);
    const int a_chalf   = a_tile >> 1;
    const int b_row     = lane & 7;
    const int b_chalf   = (lane >> 3) & 1;
    const int g  = lane >> 2;
    const int tg = lane & 3;
    const int wg = wid - 4;                      // GEMM warp 0..7
    // staging ids (GEMM threads): 256 threads, 1 chunk (8 elems) each
    const int st = (tid - 128) >> 4;             // row t (0..15)
    const int sc = (tid - 128) & 15;             // chunk (0..15)

    // ---- startup: stage W (thread owns column h = tid, 0..383)
    {
        const float* Wp = W + (size_t)nb * (DIM * 3 * DIM);
        const int h = tid;
        const int lr = h & 127;
        const uint32_t rowswz = (uint32_t)(lr & 15);
        if (h < 128) {
            #pragma unroll 4
            for (int k = 0; k < 128; k++) {
                float v = Wp[k * 384 + h];
                __nv_bfloat16 hi = __float2bfloat16(v);
                __nv_bfloat16 lo = __float2bfloat16(v - __bfloat162float(hi));
                uint32_t sw = (uint32_t)((((k >> 3) ^ rowswz) << 4) + ((k & 7) * 2));
                *(__nv_bfloat16*)(sm + OFF_WXHI + lr * 256 + sw) = hi;
                *(__nv_bfloat16*)(sm + OFF_WXLO + lr * 256 + sw) = lo;
            }
        } else {
            const uint32_t base = (h < 256) ? OFF_WF : OFF_WR2;
            #pragma unroll 4
            for (int k = 0; k < 128; k++) {
                float v = Wp[k * 384 + h];
                uint32_t sw = (uint32_t)((((k >> 3) ^ rowswz) << 4) + ((k & 7) * 2));
                *(__half*)(sm + base + lr * 256 + sw) = __float2half(v);
            }
        }
    }
    // ---- stage XB(0) (GEMM threads)
    if (!is_scan) {
        size_t o = ((size_t)bx * L_SEQ + st) * DIM + sc * 8;
        uint4 H = *(const uint4*)(g_xhi + o);
        uint4 L = *(const uint4*)(g_xlo + o);
        uint4 F = derive_f16(H, L);
        uint32_t base = OFF_XB + (uint32_t)st * 256;
        uint32_t sw = (uint32_t)((sc ^ st) << 4);
        *(uint4*)(sm + base + sw)        = H;
        *(uint4*)(sm + base + 4096 + sw) = L;
        *(uint4*)(sm + base + 8192 + sw) = F;
    }
    // ---- scan init
    const int j = tid;                           // channel (scan threads)
    float bfv = 0.0f, brv = 0.0f;
    if (is_scan) {
        bfv = bias[nb * 256 + j];
        brv = bias[nb * 256 + 128 + j];
    }
    float c = 0.0f;
    float xt[NT], xv[NT];
    __half fh[NT], rh[NT];
    __syncthreads();

    for (int i = 0; i < NTILES; i++) {
        const int buf = i & 1;
        uint4 H, L;                              // GEMM-thread prefetch regs

        if (!is_scan) {
            // -- prefetch x(i+1) (hidden under GEMM)
            if (i + 1 < NTILES) {
                size_t o = ((size_t)bx * L_SEQ + (size_t)(i + 1) * NT + st) * DIM + sc * 8;
                H = *(const uint4*)(g_xhi + o);
                L = *(const uint4*)(g_xlo + o);
            }
            // ---------- GEMM(i): warp wg owns x~-mtile wg, f-mtile wg, r-mtile wg
            float Dx[2][4], Df[2][4], Dr[2][4];
            #pragma unroll
            for (int nt = 0; nt < 2; nt++)
                #pragma unroll
                for (int e = 0; e < 4; e++) { Dx[nt][e] = 0.0f; Df[nt][e] = 0.0f; Dr[nt][e] = 0.0f; }

            const uint32_t xb = sb + OFF_XB + (uint32_t)buf * 12288;
            const int arow = wg * 16 + a_row_add;          // 0..127
            #pragma unroll
            for (int ks = 0; ks < 8; ks++) {
                uint32_t Bhi[2][2], Blo[2][2], Bf[2][2];
                #pragma unroll
                for (int nt = 0; nt < 2; nt++) {
                    int trow = nt * 8 + b_row;
                    uint32_t ba = xb + trow * 256 + (((2 * ks + b_chalf) ^ trow) << 4);
                    ldsm_x2(Bhi[nt], ba);
                    ldsm_x2(Blo[nt], ba + 4096);
                    ldsm_x2(Bf[nt],  ba + 8192);
                }
                uint32_t aoff = (uint32_t)(arow * 256 + (((2 * ks + a_chalf) ^ (arow & 15)) << 4));
                uint32_t Axh[4], Axl[4], Af[4], Ar[4];
                ldsm_x4(Axh, sb + OFF_WXHI + aoff);
                ldsm_x4(Axl, sb + OFF_WXLO + aoff);
                ldsm_x4(Af,  sb + OFF_WF   + aoff);
                ldsm_x4(Ar,  sb + OFF_WR2  + aoff);
                #pragma unroll
                for (int nt = 0; nt < 2; nt++) {
                    mma_bf16(Dx[nt], Axh, Bhi[nt]);
                    mma_bf16(Dx[nt], Axl, Bhi[nt]);
                    mma_bf16(Dx[nt], Axh, Blo[nt]);
                    mma_f16(Df[nt], Af, Bf[nt]);
                    mma_f16(Dr[nt], Ar, Bf[nt]);
                }
            }
            // -- store U(i)
            {
                int h0 = wg * 16 + g;
                float*  ux = (float*)(sm + OFF_UX);
                __half* uf = (__half*)(sm + OFF_UF);
                __half* ur = (__half*)(sm + OFF_UR);
                #pragma unroll
                for (int nt = 0; nt < 2; nt++) {
                    int t0 = nt * 8 + tg * 2;
                    ux[(t0)     * DIM + h0]     = Dx[nt][0];
                    ux[(t0 + 1) * DIM + h0]     = Dx[nt][1];
                    ux[(t0)     * DIM + h0 + 8] = Dx[nt][2];
                    ux[(t0 + 1) * DIM + h0 + 8] = Dx[nt][3];
                    uf[(t0)     * DIM + h0]     = __float2half_rn(Df[nt][0]);
                    uf[(t0 + 1) * DIM + h0]     = __float2half_rn(Df[nt][1]);
                    uf[(t0)     * DIM + h0 + 8] = __float2half_rn(Df[nt][2]);
                    uf[(t0 + 1) * DIM + h0 + 8] = __float2half_rn(Df[nt][3]);
                    ur[(t0)     * DIM + h0]     = __float2half_rn(Dr[nt][0]);
                    ur[(t0 + 1) * DIM + h0]     = __float2half_rn(Dr[nt][1]);
                    ur[(t0)     * DIM + h0 + 8] = __float2half_rn(Dr[nt][2]);
                    ur[(t0 + 1) * DIM + h0 + 8] = __float2half_rn(Dr[nt][3]);
                }
            }
        } else if (i > 0) {
            // ---------- scan(i-1), concurrent with GEMM(i)
            float* hp = g_hT + ((size_t)bx * L_SEQ + (size_t)(i - 1) * NT) * DIM + j;
            #pragma unroll
            for (int t = 0; t < NT; t++) {
                float fv = sigf(__half2float(fh[t]) + bfv);
                float rv = sigf(__half2float(rh[t]) + brv);
                c = fmaf(fv, c - xt[t], xt[t]);
                hp[t * DIM] = fmaf(rv, c - xv[t], xv[t]);
            }
        }
        __syncthreads();                         // U(i) visible; scan(i-1) done

        if (!is_scan) {
            // -- stage XB(i+1): derive F, 3 STS (buffer (i+1)&1)
            if (i + 1 < NTILES) {
                uint4 F = derive_f16(H, L);
                uint32_t base = OFF_XB + (uint32_t)((i + 1) & 1) * 12288 + (uint32_t)st * 256;
                uint32_t sw = (uint32_t)((sc ^ st) << 4);
                *(uint4*)(sm + base + sw)        = H;
                *(uint4*)(sm + base + 4096 + sw) = L;
                *(uint4*)(sm + base + 8192 + sw) = F;
            }
        } else {
            // -- drain U(i) and xv(i) into registers
            const float*  ux = (const float*)(sm + OFF_UX);
            const __half* uf = (const __half*)(sm + OFF_UF);
            const __half* ur = (const __half*)(sm + OFF_UR);
            const uint32_t xbb = OFF_XB + (uint32_t)buf * 12288;
            #pragma unroll
            for (int t = 0; t < NT; t++) {
                xt[t] = ux[t * DIM + j];
                fh[t] = uf[t * DIM + j];
                rh[t] = ur[t * DIM + j];
                uint32_t xa = xbb + t * 256 + (((j >> 3) ^ t) << 4) + ((j & 7) * 2);
                xv[t] = __bfloat162float(*(__nv_bfloat16*)(sm + xa)) +
                        __bfloat162float(*(__nv_bfloat16*)(sm + xa + 4096));
            }
        }
        __syncthreads();                         // U free; XB((i+1)&1) staged
    }

    // -- final scan(NTILES-1)
    if (is_scan) {
        float* hp = g_hT + ((size_t)bx * L_SEQ + (size_t)(NTILES - 1) * NT) * DIM + j;
        #pragma unroll
        for (int t = 0; t < NT; t++) {
            float fv = sigf(__half2float(fh[t]) + bfv);
            float rv = sigf(__half2float(rh[t]) + brv);
            c = fmaf(fv, c - xt[t], xt[t]);
            hp[t * DIM] = fmaf(rv, c - xv[t], xv[t]);
        }
    }
}

extern "C" void kernel_launch(void* const* d_in, const int* in_sizes, int n_in,
                              void* d_out, int out_size) {
    const float* x  = (const float*)d_in[0];
    const float* W  = (const float*)d_in[1];
    const float* bi = (const float*)d_in[2];
    float* out = (float*)d_out;

    transpose_x<<<(L_SEQ / TP_T) * BATCH, 256>>>(x);
    cudaFuncSetAttribute(sru_main, cudaFuncAttributeMaxDynamicSharedMemorySize, SMEM_MAIN);
    sru_main<<<BATCH * NBI, 384, SMEM_MAIN>>>(W, bi);
    untranspose_h<<<(L_SEQ / TP_T) * BATCH, 256>>>(out);
}